// round 13
// baseline (speedup 1.0000x reference)
#include <cuda_runtime.h>

#define BB 64
#define TT 512
#define DD 768
#define VV 20
#define NEGC (-1000000000.0f)
#define NCH 16            // streaming chunks per b in kA (32 tokens each)
#define TCH (TT / NCH)
#define NC3 32            // streaming chunks per b in kB (16 tokens each)
#define TC3 (TT / NC3)
#define D4 (DD / 4)       // 192 float4 per row

// Scratch (no device allocation allowed)
__device__ __align__(16) float g_p1[NCH * BB * DD];  // kA partials
__device__ __align__(16) float g_u[NC3 * BB * DD];   // kB unnormalized pooled partials
__device__ float g_m[NC3 * BB];                      // kB chunk-local max
__device__ float g_z[NC3 * BB];                      // kB chunk-local exp-sum
__device__ float g_scores[BB * TT];                  // raw pooling scores
__device__ unsigned int g_cnt1[BB];                  // kA producer arrivals (monotone)
__device__ unsigned int g_wcnt1[BB];                 // kA waiter epoch counters
__device__ unsigned int g_cnt2[BB];                  // kB producer arrivals
__device__ unsigned int g_wcnt2[BB];                 // kB waiter epochs

__device__ __forceinline__ void red_release(unsigned int* p) {
    asm volatile("red.release.gpu.global.add.u32 [%0], %1;"
                 :: "l"(p), "r"(1u) : "memory");
}
__device__ __forceinline__ unsigned int ld_acquire(const unsigned int* p) {
    unsigned int v;
    asm volatile("ld.acquire.gpu.global.u32 %0, [%1];"
                 : "=r"(v) : "l"(p) : "memory");
    return v;
}

// ---------------------------------------------------------------------------
// kA: producers (c<NCH) do masked partial sums (R8 k1 body);
//     waiter block (c==NCH) waits for its b, then does k2 (value softmax+ve).
// grid (NCH+1, BB), block 192.
// ---------------------------------------------------------------------------
__global__ __launch_bounds__(192) void kA(const float4* __restrict__ emb,
                                          const int* __restrict__ emask,
                                          const float* __restrict__ W,
                                          const int* __restrict__ vmask,
                                          float* __restrict__ out_ve,
                                          float* __restrict__ out_vp) {
    int b = blockIdx.y;
    int c = blockIdx.x;
    int tid = threadIdx.x;
    int warp = tid >> 5;
    int lane = tid & 31;

    if (c < NCH) {
        // ------------- producer: streaming masked partial sum -------------
        int t0 = c * TCH;
        __shared__ float sm[TCH];
        if (tid < TCH)
            sm[tid] = (float)emask[b * TT + t0 + tid];
        __syncthreads();

        const float4* e = emb + (size_t)(b * TT + t0) * D4 + tid;
        float4 acc = make_float4(0.f, 0.f, 0.f, 0.f);
        float4 r[8];
#pragma unroll
        for (int i = 0; i < 8; i++) r[i] = e[(size_t)i * D4];

#pragma unroll
        for (int base = 0; base < TCH; base += 8) {
            float4 n[8];
            if (base + 8 < TCH) {
#pragma unroll
                for (int i = 0; i < 8; i++)
                    n[i] = e[(size_t)(base + 8 + i) * D4];
            }
#pragma unroll
            for (int i = 0; i < 8; i++) {
                float m = sm[base + i];
                acc.x = fmaf(m, r[i].x, acc.x);
                acc.y = fmaf(m, r[i].y, acc.y);
                acc.z = fmaf(m, r[i].z, acc.z);
                acc.w = fmaf(m, r[i].w, acc.w);
            }
            if (base + 8 < TCH) {
#pragma unroll
                for (int i = 0; i < 8; i++) r[i] = n[i];
            }
        }
        ((float4*)g_p1)[(size_t)(c * BB + b) * D4 + tid] = acc;

        __syncthreads();                 // all block stores done
        if (tid == 0) red_release(&g_cnt1[b]);
        return;
    }

    // ----------------- waiter: k2 body after all 16 arrive -----------------
    __shared__ unsigned int s_tgt;
    if (tid == 0) {
        unsigned int n = atomicAdd(&g_wcnt1[b], 1u);   // epoch for this replay
        unsigned int tgt = (n + 1u) * NCH;
        while ((int)(ld_acquire(&g_cnt1[b]) - tgt) < 0)
            __nanosleep(200);
        s_tgt = tgt;
    }
    __syncthreads();   // acquire chain: tid0's acquire + cta barrier

    __shared__ float s_ms[DD];
    __shared__ float s_sc[VV];
    __shared__ float s_p[VV];

#pragma unroll
    for (int j = 0; j < 4; j++) {
        int d = tid + j * 192;
        float acc = 0.f;
#pragma unroll
        for (int cc = 0; cc < NCH; cc++)
            acc += g_p1[(size_t)(cc * BB + b) * DD + d];
        s_ms[d] = acc;
    }
    __syncthreads();

    // V dots: 6 warps x up to 4 values
#pragma unroll
    for (int k = 0; k < 4; k++) {
        int v = warp + 6 * k;
        if (v < VV) {
            const float* w = W + v * DD;
            float acc = 0.f;
#pragma unroll
            for (int d = lane; d < DD; d += 32)
                acc += s_ms[d] * w[d];
#pragma unroll
            for (int o = 16; o; o >>= 1)
                acc += __shfl_xor_sync(0xffffffffu, acc, o);
            if (lane == 0)
                s_sc[v] = acc + (1.0f - (float)vmask[b * VV + v]) * NEGC;
        }
    }
    __syncthreads();

    if (tid < 32) {
        float v = (tid < VV) ? s_sc[tid] : -3.4e38f;
        float mx = v;
#pragma unroll
        for (int o = 16; o; o >>= 1)
            mx = fmaxf(mx, __shfl_xor_sync(0xffffffffu, mx, o));
        float ev = (tid < VV) ? expf(v - mx) : 0.f;
        float s = ev;
#pragma unroll
        for (int o = 16; o; o >>= 1)
            s += __shfl_xor_sync(0xffffffffu, s, o);
        float p = ev / s;
        if (tid < VV) {
            s_p[tid] = p;
            out_vp[b * VV + tid] = p;
        }
    }
    __syncthreads();

#pragma unroll
    for (int j = 0; j < 4; j++) {
        int d = tid + j * 192;
        float acc = 0.f;
#pragma unroll
        for (int v = 0; v < VV; v++)
            acc += s_p[v] * W[v * DD + d];
        out_ve[b * DD + d] = acc;
    }
}

// ---------------------------------------------------------------------------
// kB: producers (c<NC3) do fused scores + chunk-softmax pooling (R8 k3 body);
//     waiter block (c==NC3) does the k4 combine for its b.
// grid (NC3+1, BB), block 192.
// ---------------------------------------------------------------------------
__global__ __launch_bounds__(192) void kB(const float4* __restrict__ emb,
                                          const int* __restrict__ emask,
                                          const float4* __restrict__ ve,
                                          float* __restrict__ out_pooled,
                                          float* __restrict__ out_pp) {
    int b = blockIdx.y;
    int c = blockIdx.x;
    int tid = threadIdx.x;
    int warp = tid >> 5;
    int lane = tid & 31;

    if (c < NC3) {
        // ------------- producer: scores + chunk softmax pooling -------------
        int t0 = c * TC3;
        __shared__ float red[TC3][6];
        __shared__ float s_e[TC3];

        float4 ve4 = ve[b * D4 + tid];

        const float4* e = emb + (size_t)(b * TT + t0) * D4 + tid;
        float4 r[TC3];
#pragma unroll
        for (int t = 0; t < TC3; t++)
            r[t] = e[(size_t)t * D4];

#pragma unroll
        for (int t = 0; t < TC3; t++) {
            float p = r[t].x * ve4.x + r[t].y * ve4.y +
                      r[t].z * ve4.z + r[t].w * ve4.w;
#pragma unroll
            for (int o = 16; o; o >>= 1)
                p += __shfl_xor_sync(0xffffffffu, p, o);
            if (lane == 0) red[t][warp] = p;
        }
        __syncthreads();

        if (tid < TC3) {
            float s = red[tid][0] + red[tid][1] + red[tid][2] +
                      red[tid][3] + red[tid][4] + red[tid][5];
            s += (1.0f - (float)emask[b * TT + t0 + tid]) * NEGC;
            g_scores[b * TT + t0 + tid] = s;

            float m = s;
#pragma unroll
            for (int o = 8; o; o >>= 1)
                m = fmaxf(m, __shfl_xor_sync(0x0000ffffu, m, o));
            float ez = expf(s - m);
            s_e[tid] = ez;
            float z = ez;
#pragma unroll
            for (int o = 8; o; o >>= 1)
                z += __shfl_xor_sync(0x0000ffffu, z, o);
            if (tid == 0) {
                g_m[c * BB + b] = m;
                g_z[c * BB + b] = z;
            }
        }
        __syncthreads();

        float4 acc = make_float4(0.f, 0.f, 0.f, 0.f);
#pragma unroll
        for (int t = 0; t < TC3; t++) {
            float w = s_e[t];
            acc.x = fmaf(w, r[t].x, acc.x);
            acc.y = fmaf(w, r[t].y, acc.y);
            acc.z = fmaf(w, r[t].z, acc.z);
            acc.w = fmaf(w, r[t].w, acc.w);
        }
        ((float4*)g_u)[(size_t)(c * BB + b) * D4 + tid] = acc;

        __syncthreads();
        if (tid == 0) red_release(&g_cnt2[b]);
        return;
    }

    // ----------------- waiter: k4 combine after all 32 arrive ---------------
    if (tid == 0) {
        unsigned int n = atomicAdd(&g_wcnt2[b], 1u);
        unsigned int tgt = (n + 1u) * NC3;
        while ((int)(ld_acquire(&g_cnt2[b]) - tgt) < 0)
            __nanosleep(200);
    }
    __syncthreads();

    __shared__ float s_w[NC3];
    __shared__ float s_m, s_z;

    if (tid < 32) {
        float m = g_m[tid * BB + b];
        float mm = m;
#pragma unroll
        for (int o = 16; o; o >>= 1)
            mm = fmaxf(mm, __shfl_xor_sync(0xffffffffu, mm, o));
        float w = expf(m - mm);
        s_w[tid] = w;
        float z = g_z[tid * BB + b] * w;
#pragma unroll
        for (int o = 16; o; o >>= 1)
            z += __shfl_xor_sync(0xffffffffu, z, o);
        if (tid == 0) { s_m = mm; s_z = z; }
    }
    __syncthreads();

    float inv = 1.0f / s_z;
    float gm = s_m;

    // pooled: tid = float4 column (192 == D4), 32 chunk loads, 8-deep staged
    {
        float4 acc = make_float4(0.f, 0.f, 0.f, 0.f);
        const float4* up = (const float4*)g_u;
#pragma unroll
        for (int base = 0; base < NC3; base += 8) {
            float4 u[8];
#pragma unroll
            for (int i = 0; i < 8; i++)
                u[i] = up[(size_t)((base + i) * BB + b) * D4 + tid];
#pragma unroll
            for (int i = 0; i < 8; i++) {
                float w = s_w[base + i];
                acc.x = fmaf(w, u[i].x, acc.x);
                acc.y = fmaf(w, u[i].y, acc.y);
                acc.z = fmaf(w, u[i].z, acc.z);
                acc.w = fmaf(w, u[i].w, acc.w);
            }
        }
        acc.x *= inv; acc.y *= inv; acc.z *= inv; acc.w *= inv;
        ((float4*)out_pooled)[b * D4 + tid] = acc;
    }

    // pooling probs for all tokens of b
#pragma unroll
    for (int t = tid; t < TT; t += 192)
        out_pp[b * TT + t] = expf(g_scores[b * TT + t] - gm) * inv;
}

// ---------------------------------------------------------------------------
extern "C" void kernel_launch(void* const* d_in, const int* in_sizes, int n_in,
                              void* d_out, int out_size) {
    const float* emb = (const float*)d_in[0];      // (B,T,D) f32
    const int* emask = (const int*)d_in[1];        // (B,T) i32
    const int* vmask = (const int*)d_in[2];        // (B,V) i32
    const float* W = (const float*)d_in[3];        // (V,D) f32

    float* out = (float*)d_out;
    float* out_ve = out;                            // (B,D)
    float* out_pooled = out + BB * DD;              // (B,D)
    float* out_vp = out + 2 * BB * DD;              // (B,V)
    float* out_pp = out + 2 * BB * DD + BB * VV;    // (B,T)

    kA<<<dim3(NCH + 1, BB), 192>>>((const float4*)emb, emask, W, vmask,
                                   out_ve, out_vp);
    kB<<<dim3(NC3 + 1, BB), 192>>>((const float4*)emb, emask,
                                   (const float4*)out_ve, out_pooled, out_pp);
}

// round 14
// speedup vs baseline: 1.4989x; 1.4989x over previous
#include <cuda_runtime.h>

#define BB 64
#define TT 512
#define DD 768
#define VV 20
#define NEGC (-1000000000.0f)
#define NCH 16            // t-chunks for k1
#define TCH (TT / NCH)    // 32 tokens per k1 chunk
#define NC3 32            // t-chunks for fused pooling kernel
#define TC3 (TT / NC3)    // 16 tokens per k3 chunk
#define D4 (DD / 4)       // 192 float4 per row
#define NS4 8             // k4 D-splits
#define DS4 (D4 / NS4)    // 24 float4 columns per k4 block
#define CQ (NC3 / NS4)    // 4 chunks per thread-group in k4

// Scratch (no device allocation allowed)
__device__ __align__(16) float g_p1[NCH * BB * DD];  // k1 partials
__device__ __align__(16) float g_u[NC3 * BB * DD];   // k3 unnormalized pooled partials
__device__ float g_m[NC3 * BB];                      // k3 chunk-local max
__device__ float g_z[NC3 * BB];                      // k3 chunk-local exp-sum
__device__ float g_scores[BB * TT];                  // raw pooling scores

// ---------------------------------------------------------------------------
// K1: partial masked sums — SKIPS masked rows (block-uniform predication).
// grid (NCH, B), block 192 (thread per float4 col).
// masked sum = plain sum of rows with mask==1.
// ---------------------------------------------------------------------------
__global__ __launch_bounds__(192) void k1_msum(const float4* __restrict__ emb,
                                               const int* __restrict__ emask) {
    int b = blockIdx.y;
    int c = blockIdx.x;
    int t0 = c * TCH;
    int tid = threadIdx.x;
    __shared__ int s_on[TCH];
    if (tid < TCH)
        s_on[tid] = emask[b * TT + t0 + tid];
    __syncthreads();

    const float4* e = emb + (size_t)(b * TT + t0) * D4 + tid;
    const float4 zero = make_float4(0.f, 0.f, 0.f, 0.f);
    float4 acc = zero;
    float4 r[8];
#pragma unroll
    for (int i = 0; i < 8; i++)
        r[i] = s_on[i] ? e[(size_t)i * D4] : zero;

#pragma unroll
    for (int base = 0; base < TCH; base += 8) {
        float4 n[8];
        if (base + 8 < TCH) {
#pragma unroll
            for (int i = 0; i < 8; i++)
                n[i] = s_on[base + 8 + i] ? e[(size_t)(base + 8 + i) * D4]
                                          : zero;
        }
#pragma unroll
        for (int i = 0; i < 8; i++) {
            acc.x += r[i].x; acc.y += r[i].y;
            acc.z += r[i].z; acc.w += r[i].w;
        }
        if (base + 8 < TCH) {
#pragma unroll
            for (int i = 0; i < 8; i++) r[i] = n[i];
        }
    }
    ((float4*)g_p1)[(size_t)(c * BB + b) * D4 + tid] = acc;
}

// ---------------------------------------------------------------------------
// K2: reduce msum partials, value softmax over V=20, value_embedding.
// grid B, block 768
// ---------------------------------------------------------------------------
__global__ void k2_value(const float* __restrict__ W,
                         const int* __restrict__ vmask,
                         float* __restrict__ out_ve,
                         float* __restrict__ out_vp) {
    int b = blockIdx.x;
    int tid = threadIdx.x;
    int warp = tid >> 5;
    int lane = tid & 31;
    __shared__ float s_ms[DD];
    __shared__ float s_sc[VV];
    __shared__ float s_p[VV];

    {
        float acc = 0.f;
#pragma unroll
        for (int c = 0; c < NCH; c++)
            acc += g_p1[(size_t)(c * BB + b) * DD + tid];
        s_ms[tid] = acc;
    }
    __syncthreads();

    if (warp < VV) {
        const float* w = W + warp * DD;
        float acc = 0.f;
#pragma unroll
        for (int d = lane; d < DD; d += 32)
            acc += s_ms[d] * w[d];
#pragma unroll
        for (int o = 16; o; o >>= 1)
            acc += __shfl_xor_sync(0xffffffffu, acc, o);
        if (lane == 0)
            s_sc[warp] = acc + (1.0f - (float)vmask[b * VV + warp]) * NEGC;
    }
    __syncthreads();

    if (tid < 32) {
        float v = (tid < VV) ? s_sc[tid] : -3.4e38f;
        float mx = v;
#pragma unroll
        for (int o = 16; o; o >>= 1)
            mx = fmaxf(mx, __shfl_xor_sync(0xffffffffu, mx, o));
        float ev = (tid < VV) ? expf(v - mx) : 0.f;
        float s = ev;
#pragma unroll
        for (int o = 16; o; o >>= 1)
            s += __shfl_xor_sync(0xffffffffu, s, o);
        float p = ev / s;
        if (tid < VV) {
            s_p[tid] = p;
            out_vp[b * VV + tid] = p;
        }
    }
    __syncthreads();

    float acc = 0.f;
#pragma unroll
    for (int v = 0; v < VV; v++)
        acc += s_p[v] * W[v * DD + tid];
    out_ve[b * DD + tid] = acc;
}

// ---------------------------------------------------------------------------
// K3: fused scores + chunk-softmax pooling, single emb pass — SKIPS masked
// rows entirely (load, dot, and accumulation; block-uniform branches).
// Masked tokens get score == NEGC exactly; exp underflows to 0 as in ref.
// grid (NC3, B), block 192.
// ---------------------------------------------------------------------------
__global__ __launch_bounds__(192) void k3_fused(const float4* __restrict__ emb,
                                                const int* __restrict__ emask,
                                                const float4* __restrict__ ve) {
    int b = blockIdx.y;
    int c = blockIdx.x;
    int t0 = c * TC3;
    int tid = threadIdx.x;
    int warp = tid >> 5;
    int lane = tid & 31;

    __shared__ int s_on[TC3];
    __shared__ float red[TC3][6];
    __shared__ float s_e[TC3];

    if (tid < TC3)
        s_on[tid] = emask[b * TT + t0 + tid];
    __syncthreads();

    float4 ve4 = ve[b * D4 + tid];
    const float4 zero = make_float4(0.f, 0.f, 0.f, 0.f);

    const float4* e = emb + (size_t)(b * TT + t0) * D4 + tid;
    float4 r[TC3];
#pragma unroll
    for (int t = 0; t < TC3; t++)
        r[t] = s_on[t] ? e[(size_t)t * D4] : zero;

#pragma unroll
    for (int t = 0; t < TC3; t++) {
        if (s_on[t]) {
            float p = r[t].x * ve4.x + r[t].y * ve4.y +
                      r[t].z * ve4.z + r[t].w * ve4.w;
#pragma unroll
            for (int o = 16; o; o >>= 1)
                p += __shfl_xor_sync(0xffffffffu, p, o);
            if (lane == 0) red[t][warp] = p;
        }
    }
    __syncthreads();

    if (tid < TC3) {
        float s = NEGC;
        if (s_on[tid])
            s = red[tid][0] + red[tid][1] + red[tid][2] +
                red[tid][3] + red[tid][4] + red[tid][5];
        g_scores[b * TT + t0 + tid] = s;

        float m = s;
#pragma unroll
        for (int o = 8; o; o >>= 1)
            m = fmaxf(m, __shfl_xor_sync(0x0000ffffu, m, o));
        float ez = expf(s - m);
        s_e[tid] = ez;
        float z = ez;
#pragma unroll
        for (int o = 8; o; o >>= 1)
            z += __shfl_xor_sync(0x0000ffffu, z, o);
        if (tid == 0) {
            g_m[c * BB + b] = m;
            g_z[c * BB + b] = z;
        }
    }
    __syncthreads();

    float4 acc = zero;
#pragma unroll
    for (int t = 0; t < TC3; t++) {
        if (s_on[t]) {
            float w = s_e[t];
            acc.x = fmaf(w, r[t].x, acc.x);
            acc.y = fmaf(w, r[t].y, acc.y);
            acc.z = fmaf(w, r[t].z, acc.z);
            acc.w = fmaf(w, r[t].w, acc.w);
        }
    }
    ((float4*)g_u)[(size_t)(c * BB + b) * D4 + tid] = acc;
}

// ---------------------------------------------------------------------------
// K4: combine chunk stats -> pooled embedding + pooling probs.
// grid (NS4=8, B) = 512 blocks, block 192. (R8 form — best measured)
// ---------------------------------------------------------------------------
__global__ __launch_bounds__(192) void k4_combine(float* __restrict__ out_pooled,
                                                  float* __restrict__ out_pp) {
    int b = blockIdx.y;
    int x = blockIdx.x;
    int tid = threadIdx.x;
    __shared__ float s_w[NC3];
    __shared__ float s_m, s_z;
    __shared__ float4 s_acc[NS4][DS4];

    int d_local = tid % DS4;
    int q = tid / DS4;             // 0..7
    int d = x * DS4 + d_local;
    int c0 = q * CQ;

    // prefetch u (independent of stats)
    float4 u[CQ];
#pragma unroll
    for (int i = 0; i < CQ; i++)
        u[i] = ((const float4*)g_u)[(size_t)((c0 + i) * BB + b) * D4 + d];

    // stats in warp 0, overlapped with the u loads above
    if (tid < 32) {
        float m = g_m[tid * BB + b];
        float mm = m;
#pragma unroll
        for (int o = 16; o; o >>= 1)
            mm = fmaxf(mm, __shfl_xor_sync(0xffffffffu, mm, o));
        float w = expf(m - mm);
        s_w[tid] = w;
        float z = g_z[tid * BB + b] * w;
#pragma unroll
        for (int o = 16; o; o >>= 1)
            z += __shfl_xor_sync(0xffffffffu, z, o);
        if (tid == 0) { s_m = mm; s_z = z; }
    }
    __syncthreads();

    float inv = 1.0f / s_z;
    float gm = s_m;

    float4 acc = make_float4(0.f, 0.f, 0.f, 0.f);
#pragma unroll
    for (int i = 0; i < CQ; i++) {
        float w = s_w[c0 + i];
        acc.x = fmaf(w, u[i].x, acc.x);
        acc.y = fmaf(w, u[i].y, acc.y);
        acc.z = fmaf(w, u[i].z, acc.z);
        acc.w = fmaf(w, u[i].w, acc.w);
    }
    s_acc[q][d_local] = acc;
    __syncthreads();

    if (q == 0) {
        float4 r = s_acc[0][d_local];
#pragma unroll
        for (int j = 1; j < NS4; j++) {
            float4 a = s_acc[j][d_local];
            r.x += a.x; r.y += a.y; r.z += a.z; r.w += a.w;
        }
        r.x *= inv; r.y *= inv; r.z *= inv; r.w *= inv;
        ((float4*)out_pooled)[b * D4 + d] = r;
    }

    // pp slice: 64 tokens per block-x
    if (tid < TT / NS4) {
        int t = x * (TT / NS4) + tid;
        out_pp[b * TT + t] = expf(g_scores[b * TT + t] - gm) * inv;
    }
}

// ---------------------------------------------------------------------------
extern "C" void kernel_launch(void* const* d_in, const int* in_sizes, int n_in,
                              void* d_out, int out_size) {
    const float* emb = (const float*)d_in[0];      // (B,T,D) f32
    const int* emask = (const int*)d_in[1];        // (B,T) i32
    const int* vmask = (const int*)d_in[2];        // (B,V) i32
    const float* W = (const float*)d_in[3];        // (V,D) f32

    float* out = (float*)d_out;
    float* out_ve = out;                            // (B,D)
    float* out_pooled = out + BB * DD;              // (B,D)
    float* out_vp = out + 2 * BB * DD;              // (B,V)
    float* out_pp = out + 2 * BB * DD + BB * VV;    // (B,T)

    k1_msum<<<dim3(NCH, BB), 192>>>((const float4*)emb, emask);
    k2_value<<<BB, 768>>>(W, vmask, out_ve, out_vp);
    k3_fused<<<dim3(NC3, BB), 192>>>((const float4*)emb, emask,
                                     (const float4*)out_ve);
    k4_combine<<<dim3(NS4, BB), 192>>>(out_pooled, out_pp);
}